// round 5
// baseline (speedup 1.0000x reference)
#include <cuda_runtime.h>
#include <cstdint>

typedef unsigned long long u64;
typedef unsigned int u32;

#define NMAX      250048
#define PRE_NMS   6000
#define POST_NMS  300
#define CAP       32768
#define SEGS      8
#define GRID4X    (CAP / 256)   // 128
#define IOU_THR   0.7f
#define IMG_H     1024.0f
#define IMG_W     1024.0f
#define STRIDE_F  16.0f
#define MCH       1024          // fast-path chunk for NMS bitmask
#define MWORDS    16            // 1024/64

// ---------------- device scratch (static, zero-init; self-cleaning per run) ----------------
__device__ u32    g_hist[65536];
__device__ u32    g_t16;
__device__ u32    g_candCount;
__device__ u32    g_score32[NMAX];
__device__ u64    g_cand[CAP];
__device__ u32    g_rank[CAP];
__device__ float4 g_sortedBoxes[PRE_NMS + 64];
__device__ __align__(16) u64 g_mask1024[MCH * MWORDS];
__device__ u32    g_sync4;
__device__ u32    g_sync5;

// ---------------- helpers ----------------
__device__ __forceinline__ u32 flip_score(float s) {
    u32 u = __float_as_uint(s);
    return (u & 0x80000000u) ? ~u : (u | 0x80000000u);
}

__device__ __forceinline__ float4 decode_box(const float* __restrict__ deltas,
                                             const float* __restrict__ anchors,
                                             int i) {
    float4 a = reinterpret_cast<const float4*>(anchors)[i];
    float4 d = reinterpret_cast<const float4*>(deltas)[i];
    float h = a.z - a.x;
    float w = a.w - a.y;
    float cy = a.x + 0.5f * h;
    float cx = a.y + 0.5f * w;
    float ncy = d.x * h + cy;
    float ncx = d.y * w + cx;
    float nh = expf(d.z) * h;
    float nw = expf(d.w) * w;
    float ymin = fminf(fmaxf(ncy - 0.5f * nh, 0.0f), IMG_H);
    float xmin = fminf(fmaxf(ncx - 0.5f * nw, 0.0f), IMG_W);
    float ymax = fminf(fmaxf(ncy + 0.5f * nh, 0.0f), IMG_H);
    float xmax = fminf(fmaxf(ncx + 0.5f * nw, 0.0f), IMG_W);
    return make_float4(ymin, xmin, ymax, xmax);
}

// ---------------- K1: decode + valid + flipped score + histogram ----------------
__global__ void k1_decode(const float* __restrict__ deltas,
                          const float* __restrict__ anchors,
                          const float* __restrict__ scores, int N) {
    int i = blockIdx.x * 256 + threadIdx.x;
    if (i >= N) return;
    float4 b = decode_box(deltas, anchors, i);
    bool valid = ((b.z - b.x) >= STRIDE_F) && ((b.w - b.y) >= STRIDE_F);
    u32 s = 0u;
    if (valid) {
        s = flip_score(scores[i]);
        atomicAdd(&g_hist[s >> 16], 1u);
    }
    g_score32[i] = s;
}

// ---------------- K2: 16-bit threshold; re-zeroes hist for next run ----------------
__global__ void k2_threshold() {
    __shared__ u32 ssum[1024];
    int t = threadIdx.x;
    u32 sum = 0;
    const uint4* h4 = reinterpret_cast<const uint4*>(&g_hist[t << 6]);
    #pragma unroll
    for (int b = 0; b < 16; b++) { uint4 v = h4[b]; sum += v.x + v.y + v.z + v.w; }
    ssum[t] = sum;
    __syncthreads();
    for (int off = 1; off < 1024; off <<= 1) {
        u32 v = (t + off < 1024) ? ssum[t + off] : 0u;
        __syncthreads();
        ssum[t] += v;
        __syncthreads();
    }
    u32 myCum = ssum[t];
    u32 nxtCum = (t < 1023) ? ssum[t + 1] : 0u;
    if (myCum >= PRE_NMS && nxtCum < PRE_NMS) {
        u32 running = nxtCum;
        for (int b = 63; b >= 0; b--) {
            running += g_hist[(t << 6) + b];
            if (running >= PRE_NMS) { g_t16 = (u32)((t << 6) + b); break; }
        }
    }
    if (t == 0 && ssum[0] < PRE_NMS) g_t16 = 0u;
    __syncthreads();
    #pragma unroll
    for (int k = 0; k < 64; k++) g_hist[t + (k << 10)] = 0u;   // coalesced re-zero
}

// ---------------- K3: compact candidates, block-aggregated atomics ----------------
__global__ void k3_compact(int N) {
    __shared__ u32 sCnt;
    __shared__ u32 sBase;
    int t = threadIdx.x;
    if (t == 0) sCnt = 0u;
    __syncthreads();
    int i = blockIdx.x * 256 + t;
    u32 s = (i < N) ? g_score32[i] : 0u;
    bool pass = (s != 0u) && ((s >> 16) >= g_t16);
    u32 local = 0u;
    if (pass) local = atomicAdd(&sCnt, 1u);
    __syncthreads();
    if (t == 0) sBase = (sCnt > 0u) ? atomicAdd(&g_candCount, sCnt) : 0u;
    __syncthreads();
    if (pass) {
        u32 pos = sBase + local;
        if (pos < CAP) g_cand[pos] = ((u64)s << 32) | (u32)(~(u32)i);
    }
}

// ---------------- K4: rank counts (8-way split) + last-block scatter epilogue ----------------
__global__ void k4_rank(const float* __restrict__ deltas,
                        const float* __restrict__ anchors) {
    __shared__ u64 tile[256];
    __shared__ u32 sLast;
    int C = min((int)g_candCount, CAP);
    int t = threadIdx.x;
    int rowBase = blockIdx.x * 256;
    if (rowBase < C) {
        int segLen = (C + SEGS - 1) / SEGS;
        int c0 = blockIdx.y * segLen;
        if (c0 < C) {
            int c1 = min(c0 + segLen, C);
            int row = rowBase + t;
            u64 myKey = (row < C) ? g_cand[row] : 0ull;
            int cnt = 0;
            for (int base = c0; base < c1; base += 256) {
                if (base + t < c1) tile[t] = g_cand[base + t];
                __syncthreads();
                int m = min(256, c1 - base);
                int k = 0;
                for (; k + 4 <= m; k += 4) {
                    cnt += (tile[k]   > myKey);
                    cnt += (tile[k+1] > myKey);
                    cnt += (tile[k+2] > myKey);
                    cnt += (tile[k+3] > myKey);
                }
                for (; k < m; k++) cnt += (tile[k] > myKey);
                __syncthreads();
            }
            if (row < C && cnt > 0) atomicAdd(&g_rank[row], (u32)cnt);
        }
    }
    // ---- arrival ----
    __syncthreads();
    if (t == 0) {
        __threadfence();
        u32 old = atomicAdd(&g_sync4, 1u);
        sLast = (old == gridDim.x * gridDim.y - 1u) ? 1u : 0u;
    }
    __syncthreads();
    if (!sLast) return;
    __threadfence();
    // ---- epilogue: scatter (recompute decode for candidates only) ----
    for (int i = t; i < C; i += 256) {
        u32 rank = g_rank[i];
        if (rank < PRE_NMS) {
            u64 key = g_cand[i];
            int idx = (int)(~(u32)(key & 0xFFFFFFFFull));
            g_sortedBoxes[rank] = decode_box(deltas, anchors, idx);
        }
    }
    for (int i = t; i < CAP; i += 256) g_rank[i] = 0u;   // re-zero for next run
    __syncthreads();
    if (t == 0) g_sync4 = 0u;
}

// ---------------- K5: mask over first MCH + last-block register-serial scan ----------------
__global__ void k5_nms(float* __restrict__ out) {
    __shared__ float4 sBox[MCH];
    __shared__ float  sArea[MCH];
    __shared__ u32    sLast;
    __shared__ u32    sKeptIdx[POST_NMS];
    __shared__ int    sKept;
    __shared__ float4 kb[POST_NMS];
    __shared__ float  karea[POST_NMS];

    int t = threadIdx.x;
    int n = min((int)g_candCount, PRE_NMS);

    // ---- mask phase ----
    for (int j = t; j < MCH; j += 256) {
        float4 b = (j < n) ? g_sortedBoxes[j] : make_float4(0.f, 0.f, 0.f, 0.f);
        sBox[j] = b;
        sArea[j] = (b.z - b.x) * (b.w - b.y);
    }
    __syncthreads();
    {
        int r = t & 15;
        int w = t >> 4;
        int i = blockIdx.x * 16 + r;
        u64 word = 0ull;
        int j0 = w << 6;
        if (i < n && (j0 + 63) > i) {
            float4 bi = sBox[i];
            float  ai = sArea[i];
            #pragma unroll 8
            for (int b = 0; b < 64; b++) {
                int j = j0 + b;
                float4 bj = sBox[j];
                float  aj = sArea[j];
                float iy = fmaxf(0.0f, fminf(bi.z, bj.z) - fmaxf(bi.x, bj.x));
                float ix = fmaxf(0.0f, fminf(bi.w, bj.w) - fmaxf(bi.y, bj.y));
                float inter = iy * ix;
                float iou = inter / (ai + aj - inter + 1e-9f);
                if (iou > IOU_THR && j > i) word |= (1ull << b);
            }
        }
        g_mask1024[(size_t)i * MWORDS + w] = word;
    }
    // ---- arrival ----
    __syncthreads();
    if (t == 0) {
        __threadfence();
        u32 old = atomicAdd(&g_sync5, 1u);
        sLast = (old == gridDim.x - 1u) ? 1u : 0u;
    }
    __syncthreads();
    if (!sLast) return;
    __threadfence();

    // ---- epilogue: word-serial register scan (warp 0) ----
    int m = min(n, MCH);
    if (t < 32) {
        int lane = t;
        u64 rem = 0ull;      // lane l holds removed word l (l < MWORDS)
        int kept = 0;
        int nw = (m + 63) >> 6;
        for (int wd = 0; wd < nw && kept < POST_NMS; wd++) {
            int nb = min(64, m - (wd << 6));
            u64 km = 0ull;
            int kNew = kept;
            if (lane == wd) {
                u64 rw = rem;
                for (int c = 0; c < nb && kNew < POST_NMS; c += 16) {
                    u64 rr[16];
                    int e = min(16, nb - c);
                    #pragma unroll
                    for (int b = 0; b < 16; b++)
                        rr[b] = (b < e) ? g_mask1024[(size_t)((wd << 6) + c + b) * MWORDS + wd] : 0ull;
                    #pragma unroll
                    for (int b = 0; b < 16; b++) {
                        if (b < e && kNew < POST_NMS) {
                            int bit = c + b;
                            if (!((rw >> bit) & 1ull)) {
                                rw |= rr[b];
                                km |= (1ull << bit);
                                kNew++;
                            }
                        }
                    }
                }
                rem = rw;
            }
            km   = __shfl_sync(0xffffffffu, km, wd);
            kNew = __shfl_sync(0xffffffffu, kNew, wd);
            if (lane < MWORDS) {
                u64 mm = km;
                int kbi = kept;
                while (mm) {
                    int b = __ffsll((long long)mm) - 1;
                    mm &= mm - 1;
                    if (lane != wd) rem |= g_mask1024[(size_t)((wd << 6) + b) * MWORDS + lane];
                    if (lane == 0) sKeptIdx[kbi] = (u32)((wd << 6) + b);
                    kbi++;
                }
            }
            kept = kNew;
        }
        if (lane == 0) sKept = kept;
    }
    __syncthreads();
    int kept = sKept;

    // ---- write-out: kept boxes + zero tail ----
    for (int k = t; k < POST_NMS; k += 256) {
        float4 v = (k < kept) ? g_sortedBoxes[sKeptIdx[k]] : make_float4(0.f, 0.f, 0.f, 0.f);
        reinterpret_cast<float4*>(out)[k] = v;
    }

    // ---- fallback (rare): continue incrementally past MCH ----
    if (kept < POST_NMS && n > m) {
        for (int k = t; k < kept; k += 256) {
            float4 b = g_sortedBoxes[sKeptIdx[k]];
            kb[k] = b;
            karea[k] = (b.z - b.x) * (b.w - b.y);
        }
        __syncthreads();
        for (int i = m; i < n; i++) {
            float4 b = g_sortedBoxes[i];
            float  ab = (b.z - b.x) * (b.w - b.y);
            bool sup = false;
            for (int k = t; k < kept; k += 256) {
                float4 c  = kb[k];
                float  ac = karea[k];
                float iy = fmaxf(0.0f, fminf(b.z, c.z) - fmaxf(b.x, c.x));
                float ix = fmaxf(0.0f, fminf(b.w, c.w) - fmaxf(b.y, c.y));
                float inter = iy * ix;
                float iou = inter / (ab + ac - inter + 1e-9f);
                sup = sup || (iou > IOU_THR);
            }
            int any = __syncthreads_or((int)sup);
            if (!any) {
                if (t == 0) {
                    kb[kept]    = b;
                    karea[kept] = ab;
                    reinterpret_cast<float4*>(out)[kept] = b;
                }
                kept++;
                if (kept >= POST_NMS) break;
                __syncthreads();
            }
        }
    }

    // ---- re-zero per-run scratch ----
    __syncthreads();
    if (t == 0) {
        g_candCount = 0u;
        g_sync5 = 0u;
    }
}

// ---------------- launch ----------------
extern "C" void kernel_launch(void* const* d_in, const int* in_sizes, int n_in,
                              void* d_out, int out_size) {
    const float* deltas  = (const float*)d_in[0];
    const float* anchors = (const float*)d_in[1];
    const float* scores  = (const float*)d_in[2];
    int N = in_sizes[2];
    if (N > NMAX) N = NMAX;
    float* out = (float*)d_out;

    k1_decode<<<(N + 255) / 256, 256>>>(deltas, anchors, scores, N);
    k2_threshold<<<1, 1024>>>();
    k3_compact<<<(N + 255) / 256, 256>>>(N);
    k4_rank<<<dim3(GRID4X, SEGS), 256>>>(deltas, anchors);
    k5_nms<<<MCH / 16, 256>>>(out);
}

// round 6
// speedup vs baseline: 1.6740x; 1.6740x over previous
#include <cuda_runtime.h>
#include <cstdint>

typedef unsigned long long u64;
typedef unsigned int u32;

#define NMAX      250048
#define PRE_NMS   6000
#define POST_NMS  300
#define CAP       32768
#define SEGS      32
#define IOU_THR   0.7f
#define IMG_H     1024.0f
#define IMG_W     1024.0f
#define STRIDE_F  16.0f
#define MCH       1024          // fast-path chunk for NMS bitmask
#define MWORDS    16            // 1024/64

// ---------------- device scratch (static, zero-init; self-cleaning per run) ----------------
__device__ u32    g_hist[65536];
__device__ u32    g_t16;
__device__ u32    g_candCount;
__device__ u32    g_score32[NMAX];
__device__ u64    g_cand[CAP];
__device__ u32    g_rank[CAP];
__device__ float4 g_sortedBoxes[PRE_NMS + 64];
__device__ __align__(16) u64 g_mask1024[MCH * MWORDS];

// ---------------- helpers ----------------
__device__ __forceinline__ u32 flip_score(float s) {
    u32 u = __float_as_uint(s);
    return (u & 0x80000000u) ? ~u : (u | 0x80000000u);
}

__device__ __forceinline__ float4 decode_box(const float* __restrict__ deltas,
                                             const float* __restrict__ anchors,
                                             int i) {
    float4 a = reinterpret_cast<const float4*>(anchors)[i];
    float4 d = reinterpret_cast<const float4*>(deltas)[i];
    float h = a.z - a.x;
    float w = a.w - a.y;
    float cy = a.x + 0.5f * h;
    float cx = a.y + 0.5f * w;
    float ncy = d.x * h + cy;
    float ncx = d.y * w + cx;
    float nh = expf(d.z) * h;
    float nw = expf(d.w) * w;
    float ymin = fminf(fmaxf(ncy - 0.5f * nh, 0.0f), IMG_H);
    float xmin = fminf(fmaxf(ncx - 0.5f * nw, 0.0f), IMG_W);
    float ymax = fminf(fmaxf(ncy + 0.5f * nh, 0.0f), IMG_H);
    float xmax = fminf(fmaxf(ncx + 0.5f * nw, 0.0f), IMG_W);
    return make_float4(ymin, xmin, ymax, xmax);
}

// ---------------- K1: decode + valid + flipped score + histogram ----------------
__global__ void k1_decode(const float* __restrict__ deltas,
                          const float* __restrict__ anchors,
                          const float* __restrict__ scores, int N) {
    int i = blockIdx.x * 256 + threadIdx.x;
    if (i >= N) return;
    float4 b = decode_box(deltas, anchors, i);
    bool valid = ((b.z - b.x) >= STRIDE_F) && ((b.w - b.y) >= STRIDE_F);
    u32 s = 0u;
    if (valid) {
        s = flip_score(scores[i]);
        atomicAdd(&g_hist[s >> 16], 1u);
    }
    g_score32[i] = s;
}

// ---------------- K2: 16-bit threshold; re-zeroes hist for next run ----------------
__global__ void k2_threshold() {
    __shared__ u32 ssum[1024];
    int t = threadIdx.x;
    u32 sum = 0;
    const uint4* h4 = reinterpret_cast<const uint4*>(&g_hist[t << 6]);
    #pragma unroll
    for (int b = 0; b < 16; b++) { uint4 v = h4[b]; sum += v.x + v.y + v.z + v.w; }
    ssum[t] = sum;
    __syncthreads();
    for (int off = 1; off < 1024; off <<= 1) {
        u32 v = (t + off < 1024) ? ssum[t + off] : 0u;
        __syncthreads();
        ssum[t] += v;
        __syncthreads();
    }
    u32 myCum = ssum[t];
    u32 nxtCum = (t < 1023) ? ssum[t + 1] : 0u;
    if (myCum >= PRE_NMS && nxtCum < PRE_NMS) {
        u32 running = nxtCum;
        for (int b = 63; b >= 0; b--) {
            running += g_hist[(t << 6) + b];
            if (running >= PRE_NMS) { g_t16 = (u32)((t << 6) + b); break; }
        }
    }
    if (t == 0 && ssum[0] < PRE_NMS) g_t16 = 0u;
    __syncthreads();
    #pragma unroll
    for (int k = 0; k < 64; k++) g_hist[t + (k << 10)] = 0u;   // coalesced re-zero
}

// ---------------- K3: compact candidates, block-aggregated atomics ----------------
__global__ void k3_compact(int N) {
    __shared__ u32 sCnt;
    __shared__ u32 sBase;
    int t = threadIdx.x;
    if (t == 0) sCnt = 0u;
    __syncthreads();
    int i = blockIdx.x * 256 + t;
    u32 s = (i < N) ? g_score32[i] : 0u;
    bool pass = (s != 0u) && ((s >> 16) >= g_t16);
    u32 local = 0u;
    if (pass) local = atomicAdd(&sCnt, 1u);
    __syncthreads();
    if (t == 0) sBase = (sCnt > 0u) ? atomicAdd(&g_candCount, sCnt) : 0u;
    __syncthreads();
    if (pass) {
        u32 pos = sBase + local;
        if (pos < CAP) g_cand[pos] = ((u64)s << 32) | (u32)(~(u32)i);
    }
}

// ---------------- K4a: partial rank counts (32-way column split) ----------------
__global__ void k4a_count() {
    int C = min((int)g_candCount, CAP);
    int rowBase = blockIdx.x * 256;
    if (rowBase >= C) return;
    int segLen = (C + SEGS - 1) / SEGS;
    int c0 = blockIdx.y * segLen;
    if (c0 >= C) return;
    int c1 = min(c0 + segLen, C);
    int t = threadIdx.x;
    int row = rowBase + t;
    u64 myKey = (row < C) ? g_cand[row] : 0ull;
    __shared__ u64 tile[256];
    int cnt = 0;
    for (int base = c0; base < c1; base += 256) {
        if (base + t < c1) tile[t] = g_cand[base + t];
        __syncthreads();
        int m = min(256, c1 - base);
        int k = 0;
        for (; k + 4 <= m; k += 4) {
            cnt += (tile[k]   > myKey);
            cnt += (tile[k+1] > myKey);
            cnt += (tile[k+2] > myKey);
            cnt += (tile[k+3] > myKey);
        }
        for (; k < m; k++) cnt += (tile[k] > myKey);
        __syncthreads();
    }
    if (row < C && cnt > 0) atomicAdd(&g_rank[row], (u32)cnt);
}

// ---------------- K4b: scatter (recompute decode) + re-zero ranks ----------------
__global__ void k4b_scatter(const float* __restrict__ deltas,
                            const float* __restrict__ anchors) {
    int C = min((int)g_candCount, CAP);
    int i = blockIdx.x * 256 + threadIdx.x;
    if (i >= C) return;
    u32 rank = g_rank[i];
    g_rank[i] = 0u;                        // self-clean for next run
    if (rank >= PRE_NMS) return;
    u64 key = g_cand[i];
    int idx = (int)(~(u32)(key & 0xFFFFFFFFull));
    g_sortedBoxes[rank] = decode_box(deltas, anchors, idx);
}

// ---------------- K5a: suppression bitmask over first MCH candidates ----------------
__global__ void k5a_mask() {
    __shared__ float4 sBox[MCH];
    __shared__ float  sArea[MCH];
    int n = min((int)g_candCount, PRE_NMS);
    for (int j = threadIdx.x; j < MCH; j += 256) {
        float4 b = (j < n) ? g_sortedBoxes[j] : make_float4(0.f, 0.f, 0.f, 0.f);
        sBox[j] = b;
        sArea[j] = (b.z - b.x) * (b.w - b.y);
    }
    __syncthreads();
    int r = threadIdx.x & 15;
    int w = threadIdx.x >> 4;
    int i = blockIdx.x * 16 + r;
    u64 word = 0ull;
    int j0 = w << 6;
    if (i < n && (j0 + 63) > i) {
        float4 bi = sBox[i];
        float  ai = sArea[i];
        #pragma unroll 8
        for (int b = 0; b < 64; b++) {
            int j = j0 + b;
            float4 bj = sBox[j];
            float  aj = sArea[j];
            float iy = fmaxf(0.0f, fminf(bi.z, bj.z) - fmaxf(bi.x, bj.x));
            float ix = fmaxf(0.0f, fminf(bi.w, bj.w) - fmaxf(bi.y, bj.y));
            float inter = iy * ix;
            float iou = inter / (ai + aj - inter + 1e-9f);
            if (iou > IOU_THR && j > i) word |= (1ull << b);
        }
    }
    g_mask1024[(size_t)i * MWORDS + w] = word;
}

// ---------------- K5b: sparsity-aware word-skip scan + parallel write-out ----------------
// dynamic smem: mask 128KB
__global__ void k5b_scan(float* __restrict__ out) {
    extern __shared__ char sm[];
    u64* smMask = (u64*)sm;                 // MCH*MWORDS
    __shared__ u64 sNz[MWORDS];             // bit j: mask row j nonzero
    __shared__ u64 sKeptMask[MWORDS];
    __shared__ u32 sKeptBase[MWORDS];
    __shared__ int sKept;
    __shared__ float4 kb[POST_NMS];
    __shared__ float  karea[POST_NMS];

    int t = threadIdx.x;   // 256
    int n = min((int)g_candCount, PRE_NMS);
    int m = min(n, MCH);

    if (t < MWORDS) { sNz[t] = 0ull; sKeptMask[t] = 0ull; sKeptBase[t] = 0u; }
    __syncthreads();

    // stage mask + nonzero-row flags
    {
        const float4* gm = (const float4*)g_mask1024;
        float4* dm = (float4*)smMask;
        for (int k = t; k < MCH * MWORDS / 2; k += 256) dm[k] = gm[k];
    }
    __syncthreads();
    for (int j = t; j < m; j += 256) {
        const u64* row = &smMask[j * MWORDS];
        u64 o = 0ull;
        #pragma unroll
        for (int k = 0; k < MWORDS; k++) o |= row[k];
        if (o) atomicOr(&sNz[j >> 6], 1ull << (j & 63));
    }
    __syncthreads();

    // serial word-skip scan (thread 0); rem[] lives in registers (unrolled indices)
    if (t == 0) {
        u64 rem[MWORDS];
        #pragma unroll
        for (int k = 0; k < MWORDS; k++) rem[k] = 0ull;
        int kept = 0;
        int nw = (m + 63) >> 6;
        #pragma unroll
        for (int wd = 0; wd < MWORDS; wd++) {
            if (wd >= nw || kept >= POST_NMS) break;
            int nb = min(64, m - (wd << 6));
            u64 bad = rem[wd] | sNz[wd];
            u64 kmask;
            if (bad == 0ull && kept + nb <= POST_NMS) {
                kmask = (nb == 64) ? ~0ull : ((1ull << nb) - 1ull);
                sKeptBase[wd] = (u32)kept;
                kept += nb;
            } else {
                kmask = 0ull;
                sKeptBase[wd] = (u32)kept;
                for (int b = 0; b < nb && kept < POST_NMS; b++) {
                    if (!((rem[wd] >> b) & 1ull)) {
                        kmask |= (1ull << b);
                        kept++;
                        if ((sNz[wd] >> b) & 1ull) {
                            const u64* row = &smMask[((wd << 6) + b) * MWORDS];
                            #pragma unroll
                            for (int k = 0; k < MWORDS; k++) rem[k] |= row[k];
                        }
                    }
                }
            }
            sKeptMask[wd] = kmask;
        }
        sKept = kept;
    }
    __syncthreads();
    int kept = sKept;

    // parallel write-out: expand kept masks; zero the tail
    for (int k = t; k < POST_NMS; k += 256) {
        if (k >= kept)
            reinterpret_cast<float4*>(out)[k] = make_float4(0.f, 0.f, 0.f, 0.f);
    }
    for (int j = t; j < m; j += 256) {
        int wd = j >> 6, b = j & 63;
        u64 km = sKeptMask[wd];
        if ((km >> b) & 1ull) {
            u64 below = (b == 0) ? 0ull : (km & ((1ull << b) - 1ull));
            int slot = (int)sKeptBase[wd] + __popcll(below);
            if (slot < POST_NMS)
                reinterpret_cast<float4*>(out)[slot] = g_sortedBoxes[j];
        }
    }

    // -------- fallback (rare): continue incrementally past MCH --------
    if (kept < POST_NMS && n > m) {
        __syncthreads();
        for (int k = t; k < kept; k += 256) {
            float4 b = reinterpret_cast<float4*>(out)[k];
            kb[k] = b;
            karea[k] = (b.z - b.x) * (b.w - b.y);
        }
        __syncthreads();
        for (int i = m; i < n; i++) {
            float4 b = g_sortedBoxes[i];
            float  ab = (b.z - b.x) * (b.w - b.y);
            bool sup = false;
            for (int k = t; k < kept; k += 256) {
                float4 c  = kb[k];
                float  ac = karea[k];
                float iy = fmaxf(0.0f, fminf(b.z, c.z) - fmaxf(b.x, c.x));
                float ix = fmaxf(0.0f, fminf(b.w, c.w) - fmaxf(b.y, c.y));
                float inter = iy * ix;
                float iou = inter / (ab + ac - inter + 1e-9f);
                sup = sup || (iou > IOU_THR);
            }
            int any = __syncthreads_or((int)sup);
            if (!any) {
                if (t == 0) {
                    kb[kept]    = b;
                    karea[kept] = ab;
                    reinterpret_cast<float4*>(out)[kept] = b;
                }
                kept++;
                if (kept >= POST_NMS) break;
                __syncthreads();
            }
        }
    }

    // ---- re-zero per-run scratch ----
    __syncthreads();
    if (t == 0) g_candCount = 0u;
}

// ---------------- launch ----------------
extern "C" void kernel_launch(void* const* d_in, const int* in_sizes, int n_in,
                              void* d_out, int out_size) {
    const float* deltas  = (const float*)d_in[0];
    const float* anchors = (const float*)d_in[1];
    const float* scores  = (const float*)d_in[2];
    int N = in_sizes[2];
    if (N > NMAX) N = NMAX;
    float* out = (float*)d_out;

    k1_decode<<<(N + 255) / 256, 256>>>(deltas, anchors, scores, N);
    k2_threshold<<<1, 1024>>>();
    k3_compact<<<(N + 255) / 256, 256>>>(N);
    k4a_count<<<dim3(CAP / 256, SEGS), 256>>>();
    k4b_scatter<<<CAP / 256, 256>>>(deltas, anchors);
    k5a_mask<<<MCH / 16, 256>>>();
    static const int SMEM5B = MCH * MWORDS * (int)sizeof(u64);
    cudaFuncSetAttribute(k5b_scan, cudaFuncAttributeMaxDynamicSharedMemorySize, SMEM5B);
    k5b_scan<<<1, 256, SMEM5B>>>(out);
}